// round 1
// baseline (speedup 1.0000x reference)
#include <cuda_runtime.h>
#include <cstddef>

#define Bc 48
#define Wn 8192
#define Fc 64
#define Dc 128
#define GRAM_CHUNKS 32

// Scratch (no allocations allowed): gram partials + reduced gram
__device__ float g_gram_part[Bc * GRAM_CHUNKS * Fc * Fc]; // 25.2 MB
__device__ float g_gram[Bc * Fc * Fc];                    // 786 KB

// ---------------------------------------------------------------------------
// Kernel 1: per-chunk partial Gram of row-normalized x.
// gram[b,f,g] = sum_w x[b,w,f]*x[b,w,g] / ||x[b,w,:]||^2
// grid (GRAM_CHUNKS, B), 256 threads. Each thread accumulates a 4x4 tile.
// ---------------------------------------------------------------------------
__global__ void __launch_bounds__(256) gram_partial(const float* __restrict__ x) {
    const int b = blockIdx.y;
    const int chunk = blockIdx.x;
    const int rows_per_chunk = Wn / GRAM_CHUNKS; // 256
    const int w_base = chunk * rows_per_chunk;

    __shared__ float xs[64][65];
    __shared__ float sinv2[64];

    const int t = threadIdx.x;
    const int ti = t >> 4;   // 0..15
    const int tj = t & 15;   // 0..15

    float acc[4][4] = {};
    const float* xb = x + (size_t)b * Wn * Fc;

    for (int tile = 0; tile < rows_per_chunk; tile += 64) {
        // load 64x64 rows
        for (int i = t; i < 64 * 64; i += 256) {
            int r = i >> 6, c = i & 63;
            xs[r][c] = xb[(size_t)(w_base + tile + r) * Fc + c];
        }
        __syncthreads();
        if (t < 64) {
            float s = 0.f;
            #pragma unroll
            for (int c = 0; c < 64; c++) { float v = xs[t][c]; s += v * v; }
            sinv2[t] = 1.0f / s;   // 1/||x||^2
        }
        __syncthreads();
        #pragma unroll 4
        for (int w = 0; w < 64; w++) {
            float s = sinv2[w];
            float vi[4], vj[4];
            #pragma unroll
            for (int a = 0; a < 4; a++) vi[a] = xs[w][ti + 16 * a] * s;
            #pragma unroll
            for (int a = 0; a < 4; a++) vj[a] = xs[w][tj + 16 * a];
            #pragma unroll
            for (int a = 0; a < 4; a++)
                #pragma unroll
                for (int c = 0; c < 4; c++) acc[a][c] += vi[a] * vj[c];
        }
        __syncthreads();
    }

    float* dst = g_gram_part + ((size_t)b * GRAM_CHUNKS + chunk) * (Fc * Fc);
    #pragma unroll
    for (int a = 0; a < 4; a++)
        #pragma unroll
        for (int c = 0; c < 4; c++)
            dst[(ti + 16 * a) * 64 + (tj + 16 * c)] = acc[a][c];
}

// ---------------------------------------------------------------------------
// Kernel 2: deterministic reduction of partials. grid(B), 256 threads.
// ---------------------------------------------------------------------------
__global__ void __launch_bounds__(256) gram_reduce() {
    const int b = blockIdx.x;
    const int t = threadIdx.x;
    for (int i = t; i < Fc * Fc; i += 256) {
        float s = 0.f;
        #pragma unroll
        for (int c = 0; c < GRAM_CHUNKS; c++)
            s += g_gram_part[((size_t)b * GRAM_CHUNKS + c) * (Fc * Fc) + i];
        g_gram[b * Fc * Fc + i] = s;
    }
}

// ---------------------------------------------------------------------------
// Kernel 3: fused h = contextConv(x)+ctx_b + relu(gram@seW + seb), then
// circular tokenConv -> out. One block per (batch, 64 W-rows). 512 threads.
// ---------------------------------------------------------------------------
// Shared layout (floats):
//  gram_s 4096 | cb_s 64 | cw_s 64*193 | tw_s 128*193 | xA 192 | xB 66*64 |
//  xC 192 | sew_s 66*64 | seb_s 68 | h_s 66*64
#define SM_GRAM   0
#define SM_CB     (SM_GRAM + 4096)
#define SM_CW     (SM_CB + 64)
#define SM_TW     (SM_CW + 64 * 193)
#define SM_XA     (SM_TW + 128 * 193)
#define SM_XB     (SM_XA + 192)
#define SM_XC     (SM_XB + 66 * 64)
#define SM_SEW    (SM_XC + 192)
#define SM_SEB    (SM_SEW + 66 * 64)
#define SM_H      (SM_SEB + 68)
#define SM_TOTALF (SM_H + 66 * 64)
#define SMEM_BYTES (SM_TOTALF * 4)

__global__ void __launch_bounds__(512, 1) fused_kernel(
    const float* __restrict__ x,
    const float* __restrict__ ctx_w,
    const float* __restrict__ ctx_b,
    const float* __restrict__ token_w,
    const float* __restrict__ seW_w,
    const float* __restrict__ seW_b,
    float* __restrict__ out)
{
    extern __shared__ float sm[];
    float* gram_s = sm + SM_GRAM;
    float* cb_s   = sm + SM_CB;
    float* cw_s   = sm + SM_CW;
    float* tw_s   = sm + SM_TW;
    float* xA     = sm + SM_XA;
    float* xB     = sm + SM_XB;
    float* xC     = sm + SM_XC;
    float* sew_s  = sm + SM_SEW;
    float* seb_s  = sm + SM_SEB;
    float* h_s    = sm + SM_H;

    const int b  = blockIdx.y;
    const int w0 = blockIdx.x * 64;
    const int t  = threadIdx.x;
    const float* xb = x + (size_t)b * Wn * Fc;

    // ---- stage block-invariant data ----
    for (int i = t; i < Fc * Fc; i += 512) gram_s[i] = g_gram[b * Fc * Fc + i];
    if (t < 64) cb_s[t] = ctx_b[t];
    // ctx_w [f][g][k] -> cw_s[f*193 + g*3+k]  (pad 193: conflict-free loads)
    for (int i = t; i < 64 * 192; i += 512) {
        int f = i / 192, j = i - f * 192;
        cw_s[f * 193 + j] = ctx_w[i];
    }
    // token_w [d][f][k] -> tw_s[d*193 + f*3+k]
    for (int i = t; i < 128 * 192; i += 512) {
        int d = i / 192, j = i - d * 192;
        tw_s[d * 193 + j] = token_w[i];
    }
    // main x tile: xB[j] = x[w0-1+j]  (zero pad at array bounds, contextConv)
    for (int i = t; i < 66 * 64; i += 512) {
        int j = i >> 6, c = i & 63;
        int gr = w0 - 1 + j;
        xB[i] = (gr >= 0 && gr < Wn) ? xb[(size_t)gr * Fc + c] : 0.f;
    }
    // halo x rows for wrapped h rows (hr=0 -> (w0-1)%W, hr=65 -> (w0+64)%W)
    {
        int gwlo = (w0 - 1 + Wn) % Wn;
        int gwhi = (w0 + 64) % Wn;
        for (int i = t; i < 2 * 3 * 64; i += 512) {
            int which = i / 192;
            int j = (i % 192) >> 6, c = i & 63;
            int gw = which ? gwhi : gwlo;
            int r = gw - 1 + j;
            float v = (r >= 0 && r < Wn) ? xb[(size_t)r * Fc + c] : 0.f;
            (which ? xC : xA)[j * 64 + c] = v;
        }
    }
    // seW rows for all 66 h rows (circular index)
    for (int i = t; i < 66 * 64; i += 512) {
        int hr = i >> 6, g = i & 63;
        int gw = (w0 - 1 + hr + Wn) % Wn;
        sew_s[i] = seW_w[(size_t)gw * Fc + g];
    }
    if (t < 66) {
        int gw = (w0 - 1 + t + Wn) % Wn;
        seb_s[t] = seW_b[gw];
    }
    __syncthreads();

    // ---- h phase: 66 rows x 64 f. thread = (wq 0..7, f 0..63), 4 rows each ----
    {
        const int f  = t & 63;
        const int wq = t >> 6;
        const float* cwp = cw_s + f * 193;
        for (int it = 0; it < 3; it++) {
            const int base = it * 32 + wq * 4;
            if (base >= 66) continue;
            if (base >= 1 && base <= 61) {
                // fast path: rows base..base+3 all in [1,64], contiguous x in xB
                const float* xp  = xB + (base - 1) * 64;  // rows base-1..base+4
                const float* swp = sew_s + base * 64;
                float accC[4], accS[4];
                #pragma unroll
                for (int r = 0; r < 4; r++) { accC[r] = cb_s[f]; accS[r] = seb_s[base + r]; }
                #pragma unroll 8
                for (int g = 0; g < 64; g++) {
                    float xv0 = xp[g],        xv1 = xp[64 + g],  xv2 = xp[128 + g];
                    float xv3 = xp[192 + g],  xv4 = xp[256 + g], xv5 = xp[320 + g];
                    float c0 = cwp[g * 3], c1 = cwp[g * 3 + 1], c2 = cwp[g * 3 + 2];
                    float gr = gram_s[g * 64 + f];
                    accC[0] += xv0 * c0 + xv1 * c1 + xv2 * c2;
                    accC[1] += xv1 * c0 + xv2 * c1 + xv3 * c2;
                    accC[2] += xv2 * c0 + xv3 * c1 + xv4 * c2;
                    accC[3] += xv3 * c0 + xv4 * c1 + xv5 * c2;
                    accS[0] += gr * swp[g];
                    accS[1] += gr * swp[64 + g];
                    accS[2] += gr * swp[128 + g];
                    accS[3] += gr * swp[192 + g];
                }
                #pragma unroll
                for (int r = 0; r < 4; r++)
                    h_s[(base + r) * 64 + f] = accC[r] + fmaxf(accS[r], 0.f);
            } else {
                // boundary rows (0 and 65) use their own halo x segments
                #pragma unroll
                for (int r = 0; r < 4; r++) {
                    int hr = base + r;
                    if (hr >= 66) continue;
                    const float* xp  = (hr == 0) ? xA : (hr == 65) ? xC : (xB + (hr - 1) * 64);
                    const float* swp = sew_s + hr * 64;
                    float accC = cb_s[f];
                    float accS = seb_s[hr];
                    #pragma unroll 8
                    for (int g = 0; g < 64; g++) {
                        accC += xp[g] * cwp[g * 3] + xp[64 + g] * cwp[g * 3 + 1]
                              + xp[128 + g] * cwp[g * 3 + 2];
                        accS += gram_s[g * 64 + f] * swp[g];
                    }
                    h_s[hr * 64 + f] = accC + fmaxf(accS, 0.f);
                }
            }
        }
    }
    __syncthreads();

    // ---- out phase: 64 rows x 128 d. thread = (wg 0..15, dg 0..31),
    //      tile 4w x 4d (d strided by 32 -> conflict-free weight LDS) ----
    {
        const int dg = t & 31;
        const int wg = t >> 5;
        const int wbase = wg * 4;
        float acc[4][4] = {};
        #pragma unroll 2
        for (int f = 0; f < 64; f++) {
            float hv[6];
            #pragma unroll
            for (int j = 0; j < 6; j++) hv[j] = h_s[(wbase + j) * 64 + f];
            const float* twp = tw_s + f * 3;
            #pragma unroll
            for (int k = 0; k < 3; k++) {
                float wr0 = twp[(dg)      * 193 + k];
                float wr1 = twp[(dg + 32) * 193 + k];
                float wr2 = twp[(dg + 64) * 193 + k];
                float wr3 = twp[(dg + 96) * 193 + k];
                #pragma unroll
                for (int wi = 0; wi < 4; wi++) {
                    float hvv = hv[wi + k];
                    acc[wi][0] += hvv * wr0;
                    acc[wi][1] += hvv * wr1;
                    acc[wi][2] += hvv * wr2;
                    acc[wi][3] += hvv * wr3;
                }
            }
        }
        float* ob = out + ((size_t)b * Wn + w0 + wbase) * Dc;
        #pragma unroll
        for (int wi = 0; wi < 4; wi++)
            #pragma unroll
            for (int di = 0; di < 4; di++)
                ob[wi * Dc + dg + 32 * di] = acc[wi][di];
    }
}

// ---------------------------------------------------------------------------
extern "C" void kernel_launch(void* const* d_in, const int* in_sizes, int n_in,
                              void* d_out, int out_size) {
    const float* x       = (const float*)d_in[0];
    const float* ctx_w   = (const float*)d_in[1];
    const float* ctx_b   = (const float*)d_in[2];
    const float* token_w = (const float*)d_in[3];
    const float* seW_w   = (const float*)d_in[4];
    const float* seW_b   = (const float*)d_in[5];
    float* out = (float*)d_out;

    cudaFuncSetAttribute(fused_kernel,
                         cudaFuncAttributeMaxDynamicSharedMemorySize, SMEM_BYTES);

    gram_partial<<<dim3(GRAM_CHUNKS, Bc), 256>>>(x);
    gram_reduce<<<Bc, 256>>>();
    fused_kernel<<<dim3(Wn / 64, Bc), 512, SMEM_BYTES>>>(
        x, ctx_w, ctx_b, token_w, seW_w, seW_b, out);
}